// round 10
// baseline (speedup 1.0000x reference)
#include <cuda_runtime.h>
#include <cuda_bf16.h>
#include <math.h>
#include <cstdint>

typedef unsigned long long u64;

// Problem dims (fixed by the dataset)
#define Bc   8
#define Cc   512
#define Hc   96
#define Wc   144
#define HWc  (Hc * Wc)          // 13824
#define Ntok (Bc * HWc)         // 110592
#define Dd   512
#define Mm   512

#define BK     16
#define AS_LD  68               // duplicated-A row stride (floats); 272B = 16B-aligned
#define BS_LD  516              // padded B row stride (floats); 2064B, 16B-aligned
#define A_BUF  (BK * AS_LD)     // 1088 floats per A buffer
#define B_BUF  (BK * BS_LD)     // 8256 floats per B buffer
#define EXTRA_OFF (2 * A_BUF + 2 * B_BUF)   // 18688 floats
#define SMEM_DYN  ((EXTRA_OFF + 1600) * 4)  // 81152 B

// Packed fp32x2 FMA (Blackwell FFMA2 — only reachable via PTX)
#define FMA_F32X2(d, a, b, c) \
    asm("fma.rn.f32x2 %0, %1, %2, %3;" : "=l"(d) : "l"(a), "l"(b), "l"(c))
#define UNPACK_F32X2(lo, hi, in) \
    asm("mov.b64 {%0, %1}, %2;" : "=r"(lo), "=r"(hi) : "l"(in))

#define CP_ASYNC16(dst, src) \
    asm volatile("cp.async.ca.shared.global [%0], [%1], 16;" :: "r"(dst), "l"(src))
#define CP_COMMIT()  asm volatile("cp.async.commit_group;" ::: "memory")
#define CP_WAIT0()   asm volatile("cp.async.wait_group 0;" ::: "memory")

__device__ __forceinline__ uint32_t smem_u32(const void* p) {
    uint32_t a;
    asm("{ .reg .u64 t; cvta.to.shared.u64 t, %1; cvt.u32.u64 %0, t; }"
        : "=r"(a) : "l"(p));
    return a;
}

// Scratch (allocation-free rule: __device__ globals)
__device__ float g_q[(size_t)Ntok * Dd];   // normalized q, [N, D] row-major
__device__ float g_memT[Dd * Mm];          // memory transposed: [d][m]
__device__ float g_inv[Ntok];              // 1/norm per token
__device__ float g_rowsum[Ntok];           // row softmax denominators
__device__ float g_colsum[Mm];             // column softmax denominators

// ---------------------------------------------------------------------------
// K1: per-token inverse L2 norm over channels (coalesced along hw), + zero colsum
// ---------------------------------------------------------------------------
__global__ void k_norm(const float* __restrict__ x) {
    int n = blockIdx.x * 256 + threadIdx.x;
    if (blockIdx.x == 0) {                 // zero ALL 512 entries (idempotent state)
        g_colsum[threadIdx.x]       = 0.0f;
        g_colsum[threadIdx.x + 256] = 0.0f;
    }
    if (n >= Ntok) return;
    int b = n / HWc, hw = n % HWc;
    const float* p = x + (size_t)b * Cc * HWc + hw;
    float s = 0.0f;
#pragma unroll 8
    for (int c = 0; c < Cc; c++) {
        float v = p[(size_t)c * HWc];
        s += v * v;
    }
    g_inv[n] = 1.0f / fmaxf(sqrtf(s), 1e-12f);
}

// ---------------------------------------------------------------------------
// K2: transpose mem [m][d] -> g_memT [d][m] (one-time, 1MB)
// ---------------------------------------------------------------------------
__global__ void k_prepT(const float* __restrict__ pmem) {
    __shared__ float t[32][33];
    int d0 = blockIdx.x * 32;
    int m0 = blockIdx.y * 32;
    for (int r = threadIdx.y; r < 32; r += 8)
        t[r][threadIdx.x] = pmem[(size_t)(m0 + r) * Dd + d0 + threadIdx.x];
    __syncthreads();
    for (int r = threadIdx.y; r < 32; r += 8)
        g_memT[(size_t)(d0 + r) * Mm + m0 + threadIdx.x] = t[threadIdx.x][r];
}

// ---------------------------------------------------------------------------
// K3: transpose [B,C,HW] -> g_q [N,D] with normalization, 32x32 smem tiles
// ---------------------------------------------------------------------------
__global__ void k_qt(const float* __restrict__ x) {
    __shared__ float tile[32][33];
    int b   = blockIdx.z;
    int hw0 = blockIdx.x * 32;
    int d0  = blockIdx.y * 32;
    for (int r = threadIdx.y; r < 32; r += 8)
        tile[r][threadIdx.x] =
            x[((size_t)(b * Cc + d0 + r)) * HWc + hw0 + threadIdx.x];
    __syncthreads();
    for (int r = threadIdx.y; r < 32; r += 8) {
        int n = b * HWc + hw0 + r;
        g_q[(size_t)n * Dd + d0 + threadIdx.x] = tile[threadIdx.x][r] * g_inv[n];
    }
}

// ---------------------------------------------------------------------------
// FFMA2 compute for one BK=16 k-step.
// A loads: 4 broadcast LDS.128 (duplicated pairs are contiguous); B: 2 LDS.128.
// ---------------------------------------------------------------------------
#define COMPUTE_KSTEP(As2, Bs, acc2, tg, sg)                                   \
    _Pragma("unroll")                                                          \
    for (int kk = 0; kk < BK; kk++) {                                          \
        double2 bq0 = *(const double2*)&(Bs)[kk][(sg) * 4];                    \
        double2 bq1 = *(const double2*)&(Bs)[kk][256 + (sg) * 4];              \
        u64 bb[4];                                                             \
        bb[0] = __double_as_longlong(bq0.x);                                   \
        bb[1] = __double_as_longlong(bq0.y);                                   \
        bb[2] = __double_as_longlong(bq1.x);                                   \
        bb[3] = __double_as_longlong(bq1.y);                                   \
        double2 a01 = *(const double2*)&(As2)[kk][(tg) * 8];                   \
        double2 a23 = *(const double2*)&(As2)[kk][(tg) * 8 + 4];               \
        double2 a45 = *(const double2*)&(As2)[kk][32 + (tg) * 8];              \
        double2 a67 = *(const double2*)&(As2)[kk][32 + (tg) * 8 + 4];          \
        u64 aa[8];                                                             \
        aa[0] = __double_as_longlong(a01.x); aa[1] = __double_as_longlong(a01.y); \
        aa[2] = __double_as_longlong(a23.x); aa[3] = __double_as_longlong(a23.y); \
        aa[4] = __double_as_longlong(a45.x); aa[5] = __double_as_longlong(a45.y); \
        aa[6] = __double_as_longlong(a67.x); aa[7] = __double_as_longlong(a67.y); \
        _Pragma("unroll")                                                      \
        for (int i = 0; i < 8; i++)                                            \
            _Pragma("unroll")                                                  \
            for (int jp = 0; jp < 4; jp++)                                     \
                FMA_F32X2(acc2[i][jp], aa[i], bb[jp], acc2[i][jp]);            \
    }

// ---------------------------------------------------------------------------
// Pipelined mainloop (2-stage cp.async double buffer, 1 barrier per k-step).
// SCALE mode (gemm2): A source is raw E; on staging, scale by rinv for the
// MMA operand (P), and emit out_sm = E*rinv, out_sq = E*cinv in passing.
// ---------------------------------------------------------------------------
template <bool SCALE>
__device__ __forceinline__ void run_mainloop(
    const float* __restrict__ A, const float* __restrict__ Bsrc,
    float* dynsm, uint32_t sb, int n0, int tid, int tg, int sg,
    u64 acc2[8][4], const float* cinv, float rinv,
    float* __restrict__ out_sm, float* __restrict__ out_sq) {

    const int t   = tid >> 3;
    const int kkA = (tid & 7) * 2;
    const size_t nrow = (size_t)(n0 + t);
    const size_t arow = nrow * 512 + kkA;

    // ---- prologue: stage k0=0 into buffer 0 ----
    {
#pragma unroll
        for (int i = 0; i < 8; i++) {
            int chunk = tid + i * 256;
            int r = chunk >> 7, c = (chunk & 127) * 4;
            uint32_t dst = sb + (uint32_t)(2 * A_BUF + r * BS_LD + c) * 4;
            CP_ASYNC16(dst, Bsrc + (size_t)r * 512 + c);
        }
        CP_COMMIT();
        float2 av = *(const float2*)&A[arow];
        if (SCALE) {
            float2 sm2 = make_float2(av.x * rinv, av.y * rinv);
            *(float2*)&out_sm[arow] = sm2;
            *(float2*)&out_sq[arow] =
                make_float2(av.x * cinv[kkA], av.y * cinv[kkA + 1]);
            av = sm2;
        }
        float* As0 = dynsm;
        *(float2*)&As0[kkA * AS_LD + 2 * t]       = make_float2(av.x, av.x);
        *(float2*)&As0[(kkA + 1) * AS_LD + 2 * t] = make_float2(av.y, av.y);
        CP_WAIT0();
        __syncthreads();
    }

    int buf = 0;
    for (int k0 = 0; k0 < 512; k0 += BK) {
        float2 av;
        if (k0 < 512 - BK) {
            int nb = buf ^ 1;
#pragma unroll
            for (int i = 0; i < 8; i++) {
                int chunk = tid + i * 256;
                int r = chunk >> 7, c = (chunk & 127) * 4;
                uint32_t dst = sb + (uint32_t)(2 * A_BUF + nb * B_BUF + r * BS_LD + c) * 4;
                CP_ASYNC16(dst, Bsrc + (size_t)(k0 + BK + r) * 512 + c);
            }
            CP_COMMIT();
            av = *(const float2*)&A[arow + k0 + BK];
            if (SCALE) {
                int c0 = k0 + BK + kkA;
                float2 sm2 = make_float2(av.x * rinv, av.y * rinv);
                *(float2*)&out_sm[nrow * 512 + c0] = sm2;
                *(float2*)&out_sq[nrow * 512 + c0] =
                    make_float2(av.x * cinv[c0], av.y * cinv[c0 + 1]);
                av = sm2;
            }
        }
        {
            const float (*As2)[AS_LD] = (const float(*)[AS_LD])(dynsm + buf * A_BUF);
            const float (*Bs)[BS_LD]  = (const float(*)[BS_LD])(dynsm + 2 * A_BUF + buf * B_BUF);
            COMPUTE_KSTEP(As2, Bs, acc2, tg, sg)
        }
        if (k0 < 512 - BK) {
            float* Asn = dynsm + (buf ^ 1) * A_BUF;
            Asn[kkA * AS_LD + 2 * t]           = av.x;
            Asn[kkA * AS_LD + 2 * t + 1]       = av.x;
            Asn[(kkA + 1) * AS_LD + 2 * t]     = av.y;
            Asn[(kkA + 1) * AS_LD + 2 * t + 1] = av.y;
            CP_WAIT0();
        }
        __syncthreads();
        buf ^= 1;
    }
}

// ---------------------------------------------------------------------------
// K4: GEMM1 (score = q . mem^T) fused with exp and row/col sums.
// Stores raw E = exp(score) to out_sq; rowsums to g_rowsum; colsums to g_colsum.
// ---------------------------------------------------------------------------
__global__ void __launch_bounds__(256, 2)
k_gemm1(float* __restrict__ out_sq) {
    extern __shared__ float dynsm[];
    uint32_t sb = smem_u32(dynsm);
    float* rs = dynsm + EXTRA_OFF;        // 32 floats
    float* cs = dynsm + EXTRA_OFF + 32;   // 512 floats

    int tid = threadIdx.x;
    int sg = tid & 63;
    int tg = tid >> 6;
    int n0 = blockIdx.x * 32;

    u64 acc2[8][4];
#pragma unroll
    for (int i = 0; i < 8; i++)
#pragma unroll
        for (int jp = 0; jp < 4; jp++) acc2[i][jp] = 0ull;

    run_mainloop<false>(g_q, g_memT, dynsm, sb, n0, tid, tg, sg, acc2,
                        nullptr, 0.0f, nullptr, nullptr);

    // ---- epilogue: unpack, exp, row/col reductions, store raw E ----
    float acc[8][8];
#pragma unroll
    for (int i = 0; i < 8; i++)
#pragma unroll
        for (int jp = 0; jp < 4; jp++) {
            unsigned lo, hi;
            UNPACK_F32X2(lo, hi, acc2[i][jp]);
            acc[i][2 * jp]     = __expf(__uint_as_float(lo));  // |score|<=1: no max-sub
            acc[i][2 * jp + 1] = __expf(__uint_as_float(hi));
        }

    if (tid < 32) rs[tid] = 0.0f;
    cs[tid]       = 0.0f;
    cs[tid + 256] = 0.0f;
    __syncthreads();

#pragma unroll
    for (int i = 0; i < 8; i++) {
        float p = 0.0f;
#pragma unroll
        for (int j = 0; j < 8; j++) p += acc[i][j];
        int t = (i >> 2) * 16 + tg * 4 + (i & 3);
        atomicAdd(&rs[t], p);
    }
#pragma unroll
    for (int j = 0; j < 8; j++) {
        float p = 0.0f;
#pragma unroll
        for (int i = 0; i < 8; i++) p += acc[i][j];
        int m = (j >> 2) * 256 + sg * 4 + (j & 3);
        atomicAdd(&cs[m], p);
    }
    __syncthreads();

    atomicAdd(&g_colsum[tid],       cs[tid]);
    atomicAdd(&g_colsum[tid + 256], cs[tid + 256]);
    if (tid < 32) g_rowsum[n0 + tid] = rs[tid];

#pragma unroll
    for (int i = 0; i < 8; i++) {
        int t = (i >> 2) * 16 + tg * 4 + (i & 3);
        size_t n = (size_t)(n0 + t);
#pragma unroll
        for (int sh = 0; sh < 2; sh++) {
            int m = sh * 256 + sg * 4;
            *(float4*)&out_sq[n * Mm + m] =
                make_float4(acc[i][sh * 4 + 0], acc[i][sh * 4 + 1],
                            acc[i][sh * 4 + 2], acc[i][sh * 4 + 3]);
        }
    }
}

// ---------------------------------------------------------------------------
// K5: GEMM2 (upd = P . mem) with fused score finalization: while staging A
// (raw E rows, read once chip-wide), emits out_sm = E*rinv and out_sq = E*cinv.
// Output upd written in [B, D, H, W] layout via chunked smem transpose.
// ---------------------------------------------------------------------------
__global__ void __launch_bounds__(256, 2)
k_gemm2(const float* __restrict__ pmem,
        float* __restrict__ out_sq,
        float* __restrict__ out_sm,
        float* __restrict__ out_upd) {
    extern __shared__ float dynsm[];
    uint32_t sb = smem_u32(dynsm);
    float* sT   = dynsm + EXTRA_OFF;          // [32][33]
    float* cinv = dynsm + EXTRA_OFF + 1088;   // 512 floats

    int tid = threadIdx.x;
    int sg = tid & 63;
    int tg = tid >> 6;
    int n0 = blockIdx.x * 32;

    cinv[tid]       = 1.0f / g_colsum[tid];
    cinv[tid + 256] = 1.0f / g_colsum[tid + 256];
    __syncthreads();
    float rinv = 1.0f / g_rowsum[n0 + (tid >> 3)];

    u64 acc2[8][4];
#pragma unroll
    for (int i = 0; i < 8; i++)
#pragma unroll
        for (int jp = 0; jp < 4; jp++) acc2[i][jp] = 0ull;

    run_mainloop<true>(out_sq, pmem, dynsm, sb, n0, tid, tg, sg, acc2,
                       cinv, rinv, out_sm, out_sq);

    float acc[8][8];
#pragma unroll
    for (int i = 0; i < 8; i++)
#pragma unroll
        for (int jp = 0; jp < 4; jp++) {
            unsigned lo, hi;
            UNPACK_F32X2(lo, hi, acc2[i][jp]);
            acc[i][2 * jp]     = __uint_as_float(lo);
            acc[i][2 * jp + 1] = __uint_as_float(hi);
        }

    // Output transpose: upd[(b*D + d)*HW + hw], coalesced via 32-d chunks.
    int b   = n0 / HWc;
    int hw0 = n0 % HWc;
    for (int c = 0; c < 16; c++) {
        int sh   = c >> 3;
        int sglo = (c & 7) * 8;
        if (sg >= sglo && sg < sglo + 8) {
#pragma unroll
            for (int i = 0; i < 8; i++) {
                int t = (i >> 2) * 16 + tg * 4 + (i & 3);
#pragma unroll
                for (int j = 0; j < 4; j++) {
                    int dl = (sg - sglo) * 4 + j;
                    sT[dl * 33 + t] = acc[i][sh * 4 + j];
                }
            }
        }
        __syncthreads();
        {
            int t = tid & 31;
#pragma unroll
            for (int r = 0; r < 4; r++) {
                int dl = (tid >> 5) + r * 8;
                int d  = c * 32 + dl;
                out_upd[((size_t)(b * Dd + d)) * HWc + hw0 + t] = sT[dl * 33 + t];
            }
        }
        __syncthreads();
    }
}

// ---------------------------------------------------------------------------
extern "C" void kernel_launch(void* const* d_in, const int* in_sizes, int n_in,
                              void* d_out, int out_size) {
    const float* x    = (const float*)d_in[0];   // query_source [8,512,96,144]
    const float* pmem = (const float*)d_in[1];   // memory [512,512]
    float* out = (float*)d_out;

    const size_t ND = (size_t)Ntok * Dd;         // 56,623,104
    float* out_upd = out;                        // [B, D, H, W]
    float* out_sq  = out + ND;                   // softmax over tokens [N, M]
    float* out_sm  = out + 2 * ND;               // softmax over slots  [N, M]

    // Idempotent, capture-safe (not a stream op); needed for >48KB dynamic smem
    cudaFuncSetAttribute(k_gemm1, cudaFuncAttributeMaxDynamicSharedMemorySize, SMEM_DYN);
    cudaFuncSetAttribute(k_gemm2, cudaFuncAttributeMaxDynamicSharedMemorySize, SMEM_DYN);

    k_norm<<<Ntok / 256, 256>>>(x);
    k_prepT<<<dim3(16, 16), dim3(32, 8)>>>(pmem);
    k_qt<<<dim3(HWc / 32, Dd / 32, Bc), dim3(32, 8)>>>(x);
    k_gemm1<<<Ntok / 32, 256, SMEM_DYN>>>(out_sq);
    k_gemm2<<<Ntok / 32, 256, SMEM_DYN>>>(pmem, out_sq, out_sm, out_upd);
    (void)in_sizes; (void)n_in; (void)out_size;
}